// round 9
// baseline (speedup 1.0000x reference)
#include <cuda_runtime.h>

#define H 128
#define MAXN 50000
#define MAXE 600000

// Scratch (device globals — referenced directly from device code).
__device__ __align__(16) float g_ax[MAXN * H];   // agg(x), reused all steps
__device__ __align__(16) float g_ag[MAXN * H];   // agg(c) then agg(h) per step
__device__ __align__(16) float g_h0[MAXN * H];   // initial hidden state
__device__ float g_dinv[MAXN];
__device__ int   g_deg[MAXN];
__device__ int   g_rowptr[MAXN + 1];
__device__ int   g_cursor[MAXN];
__device__ int   g_esrc[MAXE];

// ---------------- degree / norm / CSR build ----------------
__global__ void zero_deg_kernel(int n) {
    int i = blockIdx.x * blockDim.x + threadIdx.x;
    if (i < n) g_deg[i] = 0;
}

// edge_index is int32 (JAX default x64-disabled downcasts jnp.int64 -> int32)
__global__ void count_kernel(const int* __restrict__ ei, int E, int n) {
    int i = blockIdx.x * blockDim.x + threadIdx.x;
    if (i >= E) return;
    int d = ei[E + i];
    if (d >= 0 && d < n) atomicAdd(&g_deg[d], 1);
}

__global__ void dinv_kernel(int n) {
    int i = blockIdx.x * blockDim.x + threadIdx.x;
    if (i < n) g_dinv[i] = rsqrtf((float)g_deg[i] + 1.0f);
}

// single-block exclusive scan: rowptr[0]=0, rowptr[i+1]=sum(deg[0..i])
__global__ void scan_kernel(int n) {
    __shared__ int sdata[1024];
    __shared__ int s_carry;
    const int t = threadIdx.x;
    if (t == 0) { s_carry = 0; g_rowptr[0] = 0; }
    __syncthreads();
    for (int base = 0; base < n; base += 1024) {
        int v = (base + t < n) ? g_deg[base + t] : 0;
        sdata[t] = v;
        __syncthreads();
        for (int off = 1; off < 1024; off <<= 1) {
            int add = (t >= off) ? sdata[t - off] : 0;
            __syncthreads();
            sdata[t] += add;
            __syncthreads();
        }
        int incl = s_carry + sdata[t];
        if (base + t < n) {
            g_rowptr[base + t + 1] = incl;
            g_cursor[base + t] = incl - v;  // exclusive start
        }
        __syncthreads();
        if (t == 1023) s_carry = incl;
        __syncthreads();
    }
}

__global__ void fill_kernel(const int* __restrict__ ei, int E, int n) {
    int e = blockIdx.x * blockDim.x + threadIdx.x;
    if (e >= E) return;
    int s = ei[e];
    int d = ei[E + e];
    if (s < 0 || s >= n || d < 0 || d >= n) return;
    int pos = atomicAdd(&g_cursor[d], 1);
    g_esrc[pos] = s;
}

// ---------------- aggregation: out = D^-1/2 (A+I) D^-1/2 feat ----------------
// one warp per dst node; CSR gather, register accumulation, no atomics.
// feat_sel: 0 = use feat param, 1 = use g_h0. out_sel: 0 = g_ax, 1 = g_ag.
__global__ void agg_csr(const float* __restrict__ feat_in, int feat_sel, int out_sel, int n) {
    const float* feat = feat_sel ? g_h0 : feat_in;
    float* out = out_sel ? g_ag : g_ax;
    int w = (blockIdx.x * blockDim.x + threadIdx.x) >> 5;
    int lane = threadIdx.x & 31;
    if (w >= n) return;
    const float dd = g_dinv[w];
    const int col = lane << 2;
    float4 sv = *(const float4*)&feat[(size_t)w * H + col];
    float ww = dd * dd;
    float4 acc = make_float4(sv.x * ww, sv.y * ww, sv.z * ww, sv.w * ww);
    int p = g_rowptr[w], end = g_rowptr[w + 1];
    for (; p + 1 < end; p += 2) {
        int s0 = g_esrc[p];
        int s1 = g_esrc[p + 1];
        float w0 = g_dinv[s0] * dd;
        float w1 = g_dinv[s1] * dd;
        float4 v0 = *(const float4*)&feat[(size_t)s0 * H + col];
        float4 v1 = *(const float4*)&feat[(size_t)s1 * H + col];
        acc.x = fmaf(w0, v0.x, acc.x); acc.y = fmaf(w0, v0.y, acc.y);
        acc.z = fmaf(w0, v0.z, acc.z); acc.w = fmaf(w0, v0.w, acc.w);
        acc.x = fmaf(w1, v1.x, acc.x); acc.y = fmaf(w1, v1.y, acc.y);
        acc.z = fmaf(w1, v1.z, acc.z); acc.w = fmaf(w1, v1.w, acc.w);
    }
    if (p < end) {
        int s0 = g_esrc[p];
        float w0 = g_dinv[s0] * dd;
        float4 v0 = *(const float4*)&feat[(size_t)s0 * H + col];
        acc.x = fmaf(w0, v0.x, acc.x); acc.y = fmaf(w0, v0.y, acc.y);
        acc.z = fmaf(w0, v0.z, acc.z); acc.w = fmaf(w0, v0.w, acc.w);
    }
    *(float4*)&out[(size_t)w * H + col] = acc;
}

// ---------------- GEMM + fused LSTM epilogue ----------------
__device__ __forceinline__ float sigf(float x) { return 1.0f / (1.0f + expf(-x)); }

// A = [A0 | A1] (each [n,128]) from device globals, W [K,BN], tile BM=32 x BN.
// LSTM: BN=512, K=256, A0=g_ax, A1=g_ag, gates f|i|o|g in 128-col chunks.
// else: BN=128, K=128, A0 = a_sel ? g_ag : g_ax, plain bias add.
// out_sel: 0 = write to 'out' param, 1 = write to g_h0.
// out2 (LSTM only, may be null): secondary destination for h_next.
template<int BN, bool LSTM>
__global__ void __launch_bounds__(256, 2) gemm_kernel(
    const float* __restrict__ W, const float* __restrict__ bias,
    float* __restrict__ cst, float* __restrict__ out_in, float* __restrict__ out2,
    int n, int a_sel, int out_sel)
{
    constexpr int K  = LSTM ? 256 : 128;
    constexpr int BK = 16;
    constexpr int NI = BN / 64;   // column-pairs per row per thread
    __shared__ float As[BK][40];  // transposed A tile, padded
    __shared__ float Bs[BK][BN];

    const float* A0 = LSTM ? g_ax : (a_sel ? g_ag : g_ax);
    const float* A1 = g_ag;
    float* out = out_sel ? g_h0 : out_in;

    const int t  = threadIdx.x;
    const int tx = t & 31;
    const int ty = t >> 5;
    const int row0 = blockIdx.x * 32;

    float2 acc[4][NI];
#pragma unroll
    for (int r = 0; r < 4; r++)
#pragma unroll
        for (int i = 0; i < NI; i++) acc[r][i] = make_float2(0.f, 0.f);

    for (int kb = 0; kb < K; kb += BK) {
        const float* Ap = (kb < 128) ? A0 : A1;
        const int ko = kb & 127;
        if (t < 128) {
            int m  = t >> 2;
            int kq = (t & 3) << 2;
            float4 v = make_float4(0.f, 0.f, 0.f, 0.f);
            if (row0 + m < n) v = *(const float4*)&Ap[(size_t)(row0 + m) * H + ko + kq];
            As[kq + 0][m] = v.x; As[kq + 1][m] = v.y;
            As[kq + 2][m] = v.z; As[kq + 3][m] = v.w;
        }
#pragma unroll
        for (int i = 0; i < BK * BN / 1024; i++) {
            int lin = (t + (i << 8)) << 2;
            int r = lin / BN, c = lin % BN;
            *(float4*)&Bs[r][c] = *(const float4*)&W[(size_t)(kb + r) * BN + c];
        }
        __syncthreads();
#pragma unroll
        for (int k = 0; k < BK; k++) {
            float a0 = As[k][(ty << 2) + 0];
            float a1 = As[k][(ty << 2) + 1];
            float a2 = As[k][(ty << 2) + 2];
            float a3 = As[k][(ty << 2) + 3];
            float2 b[NI];
#pragma unroll
            for (int i = 0; i < NI; i++)
                b[i] = *(const float2*)&Bs[k][(i << 6) + (tx << 1)];
#pragma unroll
            for (int i = 0; i < NI; i++) {
                acc[0][i].x = fmaf(a0, b[i].x, acc[0][i].x);
                acc[0][i].y = fmaf(a0, b[i].y, acc[0][i].y);
                acc[1][i].x = fmaf(a1, b[i].x, acc[1][i].x);
                acc[1][i].y = fmaf(a1, b[i].y, acc[1][i].y);
                acc[2][i].x = fmaf(a2, b[i].x, acc[2][i].x);
                acc[2][i].y = fmaf(a2, b[i].y, acc[2][i].y);
                acc[3][i].x = fmaf(a3, b[i].x, acc[3][i].x);
                acc[3][i].y = fmaf(a3, b[i].y, acc[3][i].y);
            }
        }
        __syncthreads();
    }

#pragma unroll
    for (int r = 0; r < 4; r++) {
        int node = row0 + (ty << 2) + r;
        if (node >= n) continue;
        if constexpr (LSTM) {
#pragma unroll
            for (int i2 = 0; i2 < 2; i2++) {
                int j = (i2 << 6) + (tx << 1);
                float2 vf = acc[r][i2];
                float2 vi = acc[r][i2 + 2];
                float2 vo = acc[r][i2 + 4];
                float2 vg = acc[r][i2 + 6];
                float2 bf = *(const float2*)&bias[j];
                float2 bi = *(const float2*)&bias[128 + j];
                float2 bo = *(const float2*)&bias[256 + j];
                float2 bg = *(const float2*)&bias[384 + j];
                float2 cp = *(const float2*)&cst[(size_t)node * H + j];
                float fx = sigf(vf.x + bf.x), fy = sigf(vf.y + bf.y);
                float ix = sigf(vi.x + bi.x), iy = sigf(vi.y + bi.y);
                float ox = sigf(vo.x + bo.x), oy = sigf(vo.y + bo.y);
                float gx = tanhf(vg.x + bg.x), gy = tanhf(vg.y + bg.y);
                float2 cn = make_float2(fx * cp.x + ix * gx, fy * cp.y + iy * gy);
                float2 hn = make_float2(ox * tanhf(cn.x), oy * tanhf(cn.y));
                *(float2*)&cst[(size_t)node * H + j] = cn;
                *(float2*)&out[(size_t)node * H + j] = hn;
                if (out2) *(float2*)&out2[(size_t)node * H + j] = hn;
            }
        } else {
#pragma unroll
            for (int i = 0; i < NI; i++) {
                int j = (i << 6) + (tx << 1);
                float2 v = acc[r][i];
                float2 bb = *(const float2*)&bias[j];
                v.x += bb.x; v.y += bb.y;
                *(float2*)&out[(size_t)node * H + j] = v;
            }
        }
    }
}

// ---------------- launch ----------------
extern "C" void kernel_launch(void* const* d_in, const int* in_sizes, int n_in,
                              void* d_out, int out_size) {
    const float* x     = (const float*)d_in[0];
    const float* c     = (const float*)d_in[1];
    const int*   ei    = (const int*)d_in[2];     // int32! (JAX x64 disabled)
    const float* Wh    = (const float*)d_in[3];
    const float* bh    = (const float*)d_in[4];
    const float* Wc    = (const float*)d_in[5];
    const float* bc    = (const float*)d_in[6];
    const float* Wcell = (const float*)d_in[7];
    const float* bcell = (const float*)d_in[8];
    float* out = (float*)d_out;

    const int n = in_sizes[0] / H;
    const int E = in_sizes[2] / 2;
    const int S = in_sizes[8] / 512;

    float* hs   = out;                          // [S, n, 128]
    float* hfin = out + (size_t)S * n * H;      // [n, 128]
    float* cfin = hfin + (size_t)n * H;         // [n, 128] — live cell state

    // CSR build
    zero_deg_kernel<<<(n + 255) / 256, 256>>>(n);
    count_kernel   <<<(E + 255) / 256, 256>>>(ei, E, n);
    dinv_kernel    <<<(n + 255) / 256, 256>>>(n);
    scan_kernel    <<<1, 1024>>>(n);
    fill_kernel    <<<(E + 255) / 256, 256>>>(ei, E, n);

    const int ga = (n * 32 + 255) / 256;
    const int gb = (n + 31) / 32;

    // g_ax = agg(x) — reused for every timestep; g_ag = agg(c)
    agg_csr<<<ga, 256>>>(x, 0, 0, n);
    agg_csr<<<ga, 256>>>(c, 0, 1, n);

    // h0 = agg(x)@Wh + bh -> g_h0 ; c0 = agg(c)@Wc + bc -> c_fin slot
    gemm_kernel<128, false><<<gb, 256>>>(Wh, bh, nullptr, nullptr, nullptr, n, 0, 1);
    gemm_kernel<128, false><<<gb, 256>>>(Wc, bc, nullptr, cfin,   nullptr, n, 1, 0);

    for (int s = 0; s < S; s++) {
        if (s == 0) agg_csr<<<ga, 256>>>(nullptr, 1, 1, n);                 // agg(g_h0)
        else        agg_csr<<<ga, 256>>>(hs + (size_t)(s - 1) * n * H, 0, 1, n);
        gemm_kernel<512, true><<<gb, 256>>>(Wcell + (size_t)s * 256 * 512,
                                            bcell + (size_t)s * 512,
                                            cfin, hs + (size_t)s * n * H,
                                            (s == S - 1) ? hfin : nullptr,
                                            n, 0, 0);
    }
}